// round 1
// baseline (speedup 1.0000x reference)
#include <cuda_runtime.h>
#include <cuda_bf16.h>
#include <cstdint>

// Shapes (fixed by the problem)
#define B_   4
#define L_   4096
#define E_   1024
#define HID_ 4096
#define ROWS (B_ * L_)        // 16384
#define DH   64               // head dim
#define HEADS_ 16

// ---------------------------------------------------------------------------
// Scratch (device globals: allocation-free per harness rules)
// ---------------------------------------------------------------------------
__device__ float g_wvred[E_ * DH];                 // 256 KB
__device__ float g_S[ROWS * DH];                   // 4 MB   (== AO view 4x256x1024)
__device__ float g_AOproj[B_ * 256 * E_];          // 4 MB
__device__ float g_h1[(size_t)ROWS * E_];          // 64 MB
__device__ float g_t[(size_t)ROWS * HID_];         // 256 MB

// ---------------------------------------------------------------------------
// wv_red[e,d] = sum_h w_v[e, h*64+d]
// ---------------------------------------------------------------------------
__global__ void reduce_wv_kernel(const float* __restrict__ w_v) {
    int e = blockIdx.x;          // 0..1023
    int d = threadIdx.x;         // 0..63
    const float* row = w_v + (size_t)e * E_;
    float s = 0.f;
#pragma unroll
    for (int h = 0; h < HEADS_; h++) s += row[h * DH + d];
    g_wvred[e * DH + d] = s;
}

// ---------------------------------------------------------------------------
// S[m,d] = sum_k x[m,k] * wv_red[k,d]   (M=16384, N=64, K=1024)
// ---------------------------------------------------------------------------
__global__ __launch_bounds__(256) void gemm_S_kernel(const float* __restrict__ x) {
    int d  = threadIdx.x;                     // 0..63
    int mi = threadIdx.y;                     // 0..3
    size_t m = (size_t)blockIdx.x * 4 + mi;
    const float* xr = x + m * E_;
    float acc = 0.f;
#pragma unroll 4
    for (int k = 0; k < E_; k++) {
        acc = fmaf(xr[k], g_wvred[k * DH + d], acc);
    }
    g_S[m * DH + d] = acc;
}

// ---------------------------------------------------------------------------
// Generic 128x128x8 fp32 SGEMM, row-major A[MxK] * B[KxN] -> C[MxN]
// EPI bit0: +bias[col]   bit1: relu   bit2: +add[row,col]
// Requires M%128==0, N%128==0, K%8==0 (true for all 3 uses)
// ---------------------------------------------------------------------------
template <int EPI>
__global__ __launch_bounds__(256, 2)
void sgemm128_kernel(int M, int N, int K,
                     const float* __restrict__ A,
                     const float* __restrict__ B,
                     float* __restrict__ C,
                     const float* __restrict__ bias,
                     const float* __restrict__ add) {
    constexpr int BM = 128, BN = 128, BK = 8, TM = 8, TN = 8;
    __shared__ float As[BK][BM];
    __shared__ float Bs[BK][BN];

    const int tid  = threadIdx.x;
    const int cRow = blockIdx.y;   // M tile
    const int cCol = blockIdx.x;   // N tile

    const int tr = tid >> 4;       // 0..15
    const int tc = tid & 15;       // 0..15

    const float* Ab = A + (size_t)cRow * BM * K;
    const float* Bb = B + (size_t)cCol * BN;

    const int aRow = tid >> 1;           // 0..127
    const int aCol = (tid & 1) * 4;      // 0 or 4
    const int bRow = tid >> 5;           // 0..7
    const int bCol = (tid & 31) * 4;     // 0..124

    float acc[TM][TN] = {};

    for (int k0 = 0; k0 < K; k0 += BK) {
        float4 av = *reinterpret_cast<const float4*>(Ab + (size_t)aRow * K + k0 + aCol);
        float4 bv = *reinterpret_cast<const float4*>(Bb + (size_t)(k0 + bRow) * N + bCol);
        As[aCol + 0][aRow] = av.x;
        As[aCol + 1][aRow] = av.y;
        As[aCol + 2][aRow] = av.z;
        As[aCol + 3][aRow] = av.w;
        *reinterpret_cast<float4*>(&Bs[bRow][bCol]) = bv;
        __syncthreads();

#pragma unroll
        for (int k = 0; k < BK; k++) {
            float4 a0 = *reinterpret_cast<const float4*>(&As[k][tr * TM]);
            float4 a1 = *reinterpret_cast<const float4*>(&As[k][tr * TM + 4]);
            float4 b0 = *reinterpret_cast<const float4*>(&Bs[k][tc * TN]);
            float4 b1 = *reinterpret_cast<const float4*>(&Bs[k][tc * TN + 4]);
            float rm[TM] = {a0.x, a0.y, a0.z, a0.w, a1.x, a1.y, a1.z, a1.w};
            float rn[TN] = {b0.x, b0.y, b0.z, b0.w, b1.x, b1.y, b1.z, b1.w};
#pragma unroll
            for (int i = 0; i < TM; i++)
#pragma unroll
                for (int j = 0; j < TN; j++)
                    acc[i][j] = fmaf(rm[i], rn[j], acc[i][j]);
        }
        __syncthreads();
    }

#pragma unroll
    for (int i = 0; i < TM; i++) {
        size_t row = (size_t)cRow * BM + tr * TM + i;
#pragma unroll
        for (int j = 0; j < TN; j++) {
            int col = cCol * BN + tc * TN + j;
            float v = acc[i][j];
            if (EPI & 1) v += bias[col];
            if (EPI & 4) v += add[row * N + col];
            if (EPI & 2) v = fmaxf(v, 0.f);
            C[row * N + col] = v;
        }
    }
}

// ---------------------------------------------------------------------------
// h1[ri,:] = LN( AOproj[n, ri%256, :] + x[ri,:] ) * w + b,  one block per row
// ---------------------------------------------------------------------------
__global__ __launch_bounds__(256) void add_ln1_kernel(const float* __restrict__ x,
                                                      const float* __restrict__ w,
                                                      const float* __restrict__ b) {
    int ri = blockIdx.x;                 // 0..16383
    int n  = ri >> 12;                   // /4096
    int r  = ri & 255;
    const float* pr = g_AOproj + ((size_t)((n << 8) | r)) * E_;
    const float* xr = x + (size_t)ri * E_;
    int t = threadIdx.x;

    float v[4];
    float s = 0.f, s2 = 0.f;
#pragma unroll
    for (int i = 0; i < 4; i++) {
        int c = t + 256 * i;
        float u = pr[c] + xr[c];
        v[i] = u; s += u; s2 += u * u;
    }
    __shared__ float sh[2][8];
#pragma unroll
    for (int o = 16; o > 0; o >>= 1) {
        s  += __shfl_down_sync(0xFFFFFFFFu, s, o);
        s2 += __shfl_down_sync(0xFFFFFFFFu, s2, o);
    }
    int wid = t >> 5, lane = t & 31;
    if (lane == 0) { sh[0][wid] = s; sh[1][wid] = s2; }
    __syncthreads();
    if (t == 0) {
        float a = 0.f, c2 = 0.f;
#pragma unroll
        for (int i = 0; i < 8; i++) { a += sh[0][i]; c2 += sh[1][i]; }
        sh[0][0] = a; sh[1][0] = c2;
    }
    __syncthreads();
    float mean = sh[0][0] * (1.f / E_);
    float var  = sh[1][0] * (1.f / E_) - mean * mean;
    float rs   = rsqrtf(var + 1e-5f);
    float* orow = g_h1 + (size_t)ri * E_;
#pragma unroll
    for (int i = 0; i < 4; i++) {
        int c = t + 256 * i;
        orow[c] = (v[i] - mean) * rs * w[c] + b[c];
    }
}

// ---------------------------------------------------------------------------
// In-place LN over d_out rows (z already contains ff2 + b_ff2 + h1)
// ---------------------------------------------------------------------------
__global__ __launch_bounds__(256) void ln2_inplace_kernel(float* __restrict__ z,
                                                          const float* __restrict__ w,
                                                          const float* __restrict__ b) {
    int ri = blockIdx.x;
    float* zr = z + (size_t)ri * E_;
    int t = threadIdx.x;
    float v[4];
    float s = 0.f, s2 = 0.f;
#pragma unroll
    for (int i = 0; i < 4; i++) {
        int c = t + 256 * i;
        float u = zr[c];
        v[i] = u; s += u; s2 += u * u;
    }
    __shared__ float sh[2][8];
#pragma unroll
    for (int o = 16; o > 0; o >>= 1) {
        s  += __shfl_down_sync(0xFFFFFFFFu, s, o);
        s2 += __shfl_down_sync(0xFFFFFFFFu, s2, o);
    }
    int wid = t >> 5, lane = t & 31;
    if (lane == 0) { sh[0][wid] = s; sh[1][wid] = s2; }
    __syncthreads();
    if (t == 0) {
        float a = 0.f, c2 = 0.f;
#pragma unroll
        for (int i = 0; i < 8; i++) { a += sh[0][i]; c2 += sh[1][i]; }
        sh[0][0] = a; sh[1][0] = c2;
    }
    __syncthreads();
    float mean = sh[0][0] * (1.f / E_);
    float var  = sh[1][0] * (1.f / E_) - mean * mean;
    float rs   = rsqrtf(var + 1e-5f);
#pragma unroll
    for (int i = 0; i < 4; i++) {
        int c = t + 256 * i;
        zr[c] = (v[i] - mean) * rs * w[c] + b[c];
    }
}

// ---------------------------------------------------------------------------
// Launch
// ---------------------------------------------------------------------------
extern "C" void kernel_launch(void* const* d_in, const int* in_sizes, int n_in,
                              void* d_out, int out_size) {
    const float* x     = (const float*)d_in[0];
    // d_in[1]=w_q, d_in[2]=w_k : provably unused (softmax rows sum to 1)
    const float* w_v   = (const float*)d_in[3];
    const float* w_o   = (const float*)d_in[4];
    const float* b_o   = (const float*)d_in[5];
    const float* ln1_w = (const float*)d_in[6];
    const float* ln1_b = (const float*)d_in[7];
    const float* ln2_w = (const float*)d_in[8];
    const float* ln2_b = (const float*)d_in[9];
    const float* w_ff1 = (const float*)d_in[10];
    const float* b_ff1 = (const float*)d_in[11];
    const float* w_ff2 = (const float*)d_in[12];
    const float* b_ff2 = (const float*)d_in[13];
    float* out = (float*)d_out;

    float *p_S, *p_AOproj, *p_h1, *p_t;
    cudaGetSymbolAddress((void**)&p_S, g_S);
    cudaGetSymbolAddress((void**)&p_AOproj, g_AOproj);
    cudaGetSymbolAddress((void**)&p_h1, g_h1);
    cudaGetSymbolAddress((void**)&p_t, g_t);

    // 1) wv_red = head-sum of w_v columns
    reduce_wv_kernel<<<E_, DH>>>(w_v);

    // 2) S = x @ wv_red   (16384 x 64)
    gemm_S_kernel<<<ROWS / 4, dim3(64, 4)>>>(x);

    // 3) AOproj = S(view 1024x1024) @ w_o + b_o
    sgemm128_kernel<1><<<dim3(E_ / 128, (B_ * 256) / 128), 256>>>(
        B_ * 256, E_, E_, p_S, w_o, p_AOproj, b_o, nullptr);

    // 4) h1 = LN1(AOproj[gather] + x)
    add_ln1_kernel<<<ROWS, 256>>>(x, ln1_w, ln1_b);

    // 5) t = relu(h1 @ w_ff1 + b_ff1)
    sgemm128_kernel<3><<<dim3(HID_ / 128, ROWS / 128), 256>>>(
        ROWS, HID_, E_, p_h1, w_ff1, p_t, b_ff1, nullptr);

    // 6) out = t @ w_ff2 + b_ff2 + h1
    sgemm128_kernel<5><<<dim3(E_ / 128, ROWS / 128), 256>>>(
        ROWS, E_, HID_, p_t, w_ff2, out, b_ff2, p_h1);

    // 7) out = LN2(out) in-place
    ln2_inplace_kernel<<<ROWS, 256>>>(out, ln2_w, ln2_b);
}

// round 3
// speedup vs baseline: 2.5152x; 2.5152x over previous
#include <cuda_runtime.h>
#include <cuda_bf16.h>
#include <cstdint>

// Shapes (fixed by the problem)
#define B_   4
#define L_   4096
#define E_   1024
#define HID_ 4096
#define ROWS (B_ * L_)        // 16384
#define DH   64               // head dim
#define HEADS_ 16

// ---------------------------------------------------------------------------
// PTX helpers (sm_103-safe: no tcgen05 — ptxas target lacks the 'a' features)
// ---------------------------------------------------------------------------
__device__ __forceinline__ uint32_t smem_to_u32(const void* p) {
    uint32_t a;
    asm("{ .reg .u64 t; cvta.to.shared.u64 t, %1; cvt.u32.u64 %0, t; }" : "=r"(a) : "l"(p));
    return a;
}
#define CP_ASYNC16(dst, src) asm volatile("cp.async.cg.shared.global [%0], [%1], 16;" :: "r"((uint32_t)(dst)), "l"(src) : "memory")
#define CP_COMMIT()          asm volatile("cp.async.commit_group;" ::: "memory")
#define CP_WAIT(N)           asm volatile("cp.async.wait_group %0;" :: "n"(N) : "memory")

#define LDM_X4(r0, r1, r2, r3, addr) \
    asm volatile("ldmatrix.sync.aligned.m8n8.x4.shared.b16 {%0,%1,%2,%3}, [%4];" \
        : "=r"(r0), "=r"(r1), "=r"(r2), "=r"(r3) : "r"(addr))

__device__ __forceinline__ void mma_bf16(float* c, const uint32_t* a, const uint32_t* b) {
    asm volatile("mma.sync.aligned.m16n8k16.row.col.f32.bf16.bf16.f32 "
        "{%0,%1,%2,%3}, {%4,%5,%6,%7}, {%8,%9}, {%0,%1,%2,%3};"
        : "+f"(c[0]), "+f"(c[1]), "+f"(c[2]), "+f"(c[3])
        : "r"(a[0]), "r"(a[1]), "r"(a[2]), "r"(a[3]), "r"(b[0]), "r"(b[1]));
}

// 16B-granular XOR swizzle: rows in 64B, conflict-free ldmatrix across 8 rows
#define SWZ(r) ((((r) >> 1) & 3) << 4)

// ---------------------------------------------------------------------------
// Scratch (device globals)
// ---------------------------------------------------------------------------
__device__ float g_wvred[E_ * DH];
__device__ float g_S[ROWS * DH];
__device__ float g_AOproj[B_ * 256 * E_];
__device__ float g_h1[(size_t)ROWS * E_];
__device__ __nv_bfloat16 g_h1h[(size_t)ROWS * E_];
__device__ __nv_bfloat16 g_h1l[(size_t)ROWS * E_];
__device__ __nv_bfloat16 g_th[(size_t)ROWS * HID_];
__device__ __nv_bfloat16 g_tl[(size_t)ROWS * HID_];
__device__ __nv_bfloat16 g_wt1h[(size_t)HID_ * E_];
__device__ __nv_bfloat16 g_wt1l[(size_t)HID_ * E_];
__device__ __nv_bfloat16 g_wt2h[(size_t)HID_ * E_];
__device__ __nv_bfloat16 g_wt2l[(size_t)HID_ * E_];

// ---------------------------------------------------------------------------
// wv_red[e,d] = sum_h w_v[e, h*64+d]
// ---------------------------------------------------------------------------
__global__ void reduce_wv_kernel(const float* __restrict__ w_v) {
    int e = blockIdx.x, d = threadIdx.x;
    const float* row = w_v + (size_t)e * E_;
    float s = 0.f;
#pragma unroll
    for (int h = 0; h < HEADS_; h++) s += row[h * DH + d];
    g_wvred[e * DH + d] = s;
}

// ---------------------------------------------------------------------------
// S = x @ wv_red   (16384 x 64, K=1024)
// ---------------------------------------------------------------------------
__global__ __launch_bounds__(256) void gemm_S_kernel(const float* __restrict__ x) {
    int d = threadIdx.x, mi = threadIdx.y;
    size_t m = (size_t)blockIdx.x * 4 + mi;
    const float* xr = x + m * E_;
    float acc = 0.f;
#pragma unroll 4
    for (int k = 0; k < E_; k++) acc = fmaf(xr[k], g_wvred[k * DH + d], acc);
    g_S[m * DH + d] = acc;
}

// ---------------------------------------------------------------------------
// fp32 SGEMM 128x128x8 (only for the small 1024^3 w_o GEMM)
// ---------------------------------------------------------------------------
__global__ __launch_bounds__(256, 2)
void sgemm128_kernel(int M, int N, int K,
                     const float* __restrict__ A, const float* __restrict__ B,
                     float* __restrict__ C, const float* __restrict__ bias) {
    constexpr int BM = 128, BN = 128, BK = 8, TM = 8, TN = 8;
    __shared__ float As[BK][BM];
    __shared__ float Bs[BK][BN];
    const int tid = threadIdx.x;
    const int cRow = blockIdx.y, cCol = blockIdx.x;
    const int tr = tid >> 4, tc = tid & 15;
    const float* Ab = A + (size_t)cRow * BM * K;
    const float* Bb = B + (size_t)cCol * BN;
    const int aRow = tid >> 1, aCol = (tid & 1) * 4;
    const int bRow = tid >> 5, bCol = (tid & 31) * 4;
    float acc[TM][TN] = {};
    for (int k0 = 0; k0 < K; k0 += BK) {
        float4 av = *reinterpret_cast<const float4*>(Ab + (size_t)aRow * K + k0 + aCol);
        float4 bv = *reinterpret_cast<const float4*>(Bb + (size_t)(k0 + bRow) * N + bCol);
        As[aCol + 0][aRow] = av.x; As[aCol + 1][aRow] = av.y;
        As[aCol + 2][aRow] = av.z; As[aCol + 3][aRow] = av.w;
        *reinterpret_cast<float4*>(&Bs[bRow][bCol]) = bv;
        __syncthreads();
#pragma unroll
        for (int k = 0; k < BK; k++) {
            float4 a0 = *reinterpret_cast<const float4*>(&As[k][tr * TM]);
            float4 a1 = *reinterpret_cast<const float4*>(&As[k][tr * TM + 4]);
            float4 b0 = *reinterpret_cast<const float4*>(&Bs[k][tc * TN]);
            float4 b1 = *reinterpret_cast<const float4*>(&Bs[k][tc * TN + 4]);
            float rm[TM] = {a0.x, a0.y, a0.z, a0.w, a1.x, a1.y, a1.z, a1.w};
            float rn[TN] = {b0.x, b0.y, b0.z, b0.w, b1.x, b1.y, b1.z, b1.w};
#pragma unroll
            for (int i = 0; i < TM; i++)
#pragma unroll
                for (int j = 0; j < TN; j++) acc[i][j] = fmaf(rm[i], rn[j], acc[i][j]);
        }
        __syncthreads();
    }
#pragma unroll
    for (int i = 0; i < TM; i++) {
        size_t row = (size_t)cRow * BM + tr * TM + i;
#pragma unroll
        for (int j = 0; j < TN; j++) {
            int col = cCol * BN + tc * TN + j;
            C[row * N + col] = acc[i][j] + bias[col];
        }
    }
}

// ---------------------------------------------------------------------------
// Transpose + split fp32 -> (hi, lo) bf16.  out[c, r] = split(in[r, c])
// ---------------------------------------------------------------------------
__global__ __launch_bounds__(256) void transpose_split_kernel(
    const float* __restrict__ W, int R, int C,
    __nv_bfloat16* __restrict__ Thi, __nv_bfloat16* __restrict__ Tlo) {
    __shared__ float tile[32][33];
    int r0 = blockIdx.y * 32, c0 = blockIdx.x * 32;
    int tx = threadIdx.x, ty = threadIdx.y;
#pragma unroll
    for (int j = 0; j < 4; j++)
        tile[ty + 8 * j][tx] = W[(size_t)(r0 + ty + 8 * j) * C + c0 + tx];
    __syncthreads();
#pragma unroll
    for (int j = 0; j < 4; j++) {
        float v = tile[tx][ty + 8 * j];
        __nv_bfloat16 hi = __float2bfloat16(v);
        __nv_bfloat16 lo = __float2bfloat16(v - __bfloat162float(hi));
        size_t o = (size_t)(c0 + ty + 8 * j) * R + r0 + tx;
        Thi[o] = hi; Tlo[o] = lo;
    }
}

// ---------------------------------------------------------------------------
// h1 = LN1(AOproj[gather] + x); also emit bf16 hi/lo split of h1
// ---------------------------------------------------------------------------
__global__ __launch_bounds__(256) void add_ln1_kernel(const float* __restrict__ x,
                                                      const float* __restrict__ w,
                                                      const float* __restrict__ b) {
    int ri = blockIdx.x;
    int n = ri >> 12, r = ri & 255;
    const float* pr = g_AOproj + ((size_t)((n << 8) | r)) * E_;
    const float* xr = x + (size_t)ri * E_;
    int t = threadIdx.x;
    float v[4]; float s = 0.f, s2 = 0.f;
#pragma unroll
    for (int i = 0; i < 4; i++) {
        int c = t + 256 * i;
        float u = pr[c] + xr[c];
        v[i] = u; s += u; s2 += u * u;
    }
    __shared__ float sh[2][8];
#pragma unroll
    for (int o = 16; o > 0; o >>= 1) {
        s  += __shfl_down_sync(0xFFFFFFFFu, s, o);
        s2 += __shfl_down_sync(0xFFFFFFFFu, s2, o);
    }
    int wid = t >> 5, lane = t & 31;
    if (lane == 0) { sh[0][wid] = s; sh[1][wid] = s2; }
    __syncthreads();
    if (t == 0) {
        float a = 0.f, c2 = 0.f;
#pragma unroll
        for (int i = 0; i < 8; i++) { a += sh[0][i]; c2 += sh[1][i]; }
        sh[0][0] = a; sh[1][0] = c2;
    }
    __syncthreads();
    float mean = sh[0][0] * (1.f / E_);
    float var  = sh[1][0] * (1.f / E_) - mean * mean;
    float rs   = rsqrtf(var + 1e-5f);
    float* orow = g_h1 + (size_t)ri * E_;
    __nv_bfloat16* hrow = g_h1h + (size_t)ri * E_;
    __nv_bfloat16* lrow = g_h1l + (size_t)ri * E_;
#pragma unroll
    for (int i = 0; i < 4; i++) {
        int c = t + 256 * i;
        float u = (v[i] - mean) * rs * w[c] + b[c];
        orow[c] = u;
        __nv_bfloat16 hi = __float2bfloat16(u);
        hrow[c] = hi;
        lrow[c] = __float2bfloat16(u - __bfloat162float(hi));
    }
}

// ---------------------------------------------------------------------------
// Split-bf16 HMMA GEMM (mma.sync m16n8k16): C[M,N] = A[M,K] @ B[N,K]^T
// EPI 1: relu(acc + bias) -> bf16 hi/lo split (Chi, Clo)
// EPI 2: acc + bias + add -> fp32 (Cf)
// Block 128x128, BK=32, 8 warps (each 64x32), 3-stage cp.async pipeline.
// Stage layout: Ahi | Alo | Bhi | Blo, each 128 rows x 64B (SWZ 16B swizzle)
// ---------------------------------------------------------------------------
#define ST_BYTES 32768
#define SMEM_BYTES (3 * ST_BYTES)

__device__ __forceinline__ void load_stage(uint32_t sm,
    const __nv_bfloat16* Ah, const __nv_bfloat16* Al,
    const __nv_bfloat16* Bh, const __nv_bfloat16* Bl,
    int K, int k0, int tid) {
    const __nv_bfloat16* srcs[4] = {Ah, Al, Bh, Bl};
#pragma unroll
    for (int a4 = 0; a4 < 4; a4++) {
        const __nv_bfloat16* src = srcs[a4] + k0;
        uint32_t base = sm + a4 * 8192;
#pragma unroll
        for (int j = 0; j < 2; j++) {
            int i = tid + 256 * j;
            int row = i >> 2, c = i & 3;
            CP_ASYNC16(base + row * 64 + ((c * 16) ^ SWZ(row)),
                       src + (size_t)row * K + c * 8);
        }
    }
}

template <int EPI>
__global__ __launch_bounds__(256, 1)
void hmma_gemm_kernel(int M, int N, int K,
                      const __nv_bfloat16* __restrict__ Ahi, const __nv_bfloat16* __restrict__ Alo,
                      const __nv_bfloat16* __restrict__ Bhi, const __nv_bfloat16* __restrict__ Blo,
                      const float* __restrict__ bias, const float* __restrict__ add,
                      float* __restrict__ Cf,
                      __nv_bfloat16* __restrict__ Chi, __nv_bfloat16* __restrict__ Clo) {
    extern __shared__ char smem[];
    uint32_t sbase = smem_to_u32(smem);
    const int tid = threadIdx.x, lane = tid & 31, wid = tid >> 5;
    const int wm = wid & 1, wn = wid >> 1;   // warp tile: 64x32 at (wm*64, wn*32)

    const __nv_bfloat16* Ah = Ahi + (size_t)blockIdx.y * 128 * K;
    const __nv_bfloat16* Al = Alo + (size_t)blockIdx.y * 128 * K;
    const __nv_bfloat16* Bh = Bhi + (size_t)blockIdx.x * 128 * K;
    const __nv_bfloat16* Bl = Blo + (size_t)blockIdx.x * 128 * K;

    float acc[4][4][4] = {};

    const int la15 = lane & 15;              // A ldmatrix row-in-tile
    const int khA  = lane >> 4;              // A k-half
    const int lbB  = (lane & 7) + ((lane & 16) >> 1);   // B row-in-16 (n)
    const int khB  = (lane >> 3) & 1;        // B k-half

    const int nc = K / 32;
#pragma unroll
    for (int c = 0; c < 3; c++) {
        load_stage(sbase + c * ST_BYTES, Ah, Al, Bh, Bl, K, c * 32, tid);
        CP_COMMIT();
    }

    for (int c = 0; c < nc; c++) {
        int rem = nc - 1 - c;
        if (rem >= 2)      CP_WAIT(2);
        else if (rem == 1) CP_WAIT(1);
        else               CP_WAIT(0);
        __syncthreads();

        uint32_t st  = sbase + (c % 3) * ST_BYTES;
        uint32_t sAh = st, sAl = st + 8192, sBh = st + 16384, sBl = st + 24576;

#pragma unroll
        for (int ks = 0; ks < 2; ks++) {
            uint32_t a_[4][4], bh_[4][2], bl_[4][2];
            uint32_t kbA = ks * 32 + khA * 16;
            uint32_t kbB = ks * 32 + khB * 16;
#pragma unroll
            for (int mt = 0; mt < 4; mt++) {
                int r = wm * 64 + mt * 16 + la15;
                LDM_X4(a_[mt][0], a_[mt][1], a_[mt][2], a_[mt][3],
                       sAh + r * 64 + (kbA ^ SWZ(r)));
            }
#pragma unroll
            for (int np = 0; np < 2; np++) {
                int r = wn * 32 + np * 16 + lbB;
                uint32_t off = r * 64 + (kbB ^ SWZ(r));
                LDM_X4(bh_[2 * np][0], bh_[2 * np][1], bh_[2 * np + 1][0], bh_[2 * np + 1][1],
                       sBh + off);
                LDM_X4(bl_[2 * np][0], bl_[2 * np][1], bl_[2 * np + 1][0], bl_[2 * np + 1][1],
                       sBl + off);
            }
#pragma unroll
            for (int mt = 0; mt < 4; mt++)
#pragma unroll
                for (int nt = 0; nt < 4; nt++) {
                    mma_bf16(acc[mt][nt], a_[mt], bh_[nt]);   // hi*hi
                    mma_bf16(acc[mt][nt], a_[mt], bl_[nt]);   // hi*lo
                }
#pragma unroll
            for (int mt = 0; mt < 4; mt++) {
                int r = wm * 64 + mt * 16 + la15;
                LDM_X4(a_[mt][0], a_[mt][1], a_[mt][2], a_[mt][3],
                       sAl + r * 64 + (kbA ^ SWZ(r)));
            }
#pragma unroll
            for (int mt = 0; mt < 4; mt++)
#pragma unroll
                for (int nt = 0; nt < 4; nt++)
                    mma_bf16(acc[mt][nt], a_[mt], bh_[nt]);   // lo*hi
        }
        __syncthreads();

        if (c + 3 < nc) {
            load_stage(st, Ah, Al, Bh, Bl, K, (c + 3) * 32, tid);
            CP_COMMIT();
        }
    }

    // Epilogue: fragment layout c0,c1 -> (row l/4, col (l&3)*2); c2,c3 -> row+8
    int rb = blockIdx.y * 128 + wm * 64 + (lane >> 2);
    int cb = blockIdx.x * 128 + wn * 32 + (lane & 3) * 2;
#pragma unroll
    for (int mt = 0; mt < 4; mt++)
#pragma unroll
        for (int h = 0; h < 2; h++) {
            size_t row = (size_t)rb + mt * 16 + h * 8;
#pragma unroll
            for (int nt = 0; nt < 4; nt++) {
                int col = cb + nt * 8;
                float v0 = acc[mt][nt][2 * h + 0];
                float v1 = acc[mt][nt][2 * h + 1];
                if (EPI == 1) {
                    v0 = fmaxf(v0 + bias[col], 0.f);
                    v1 = fmaxf(v1 + bias[col + 1], 0.f);
                    __nv_bfloat16 h0 = __float2bfloat16(v0), h1b = __float2bfloat16(v1);
                    __nv_bfloat16 l0 = __float2bfloat16(v0 - __bfloat162float(h0));
                    __nv_bfloat16 l1 = __float2bfloat16(v1 - __bfloat162float(h1b));
                    __nv_bfloat162 ph; ph.x = h0; ph.y = h1b;
                    __nv_bfloat162 pl; pl.x = l0; pl.y = l1;
                    *reinterpret_cast<__nv_bfloat162*>(Chi + row * N + col) = ph;
                    *reinterpret_cast<__nv_bfloat162*>(Clo + row * N + col) = pl;
                } else {
                    float2 av = *reinterpret_cast<const float2*>(add + row * N + col);
                    float2 o;
                    o.x = v0 + bias[col]     + av.x;
                    o.y = v1 + bias[col + 1] + av.y;
                    *reinterpret_cast<float2*>(Cf + row * N + col) = o;
                }
            }
        }
}

// ---------------------------------------------------------------------------
// LN2 in-place over d_out rows
// ---------------------------------------------------------------------------
__global__ __launch_bounds__(256) void ln2_inplace_kernel(float* __restrict__ z,
                                                          const float* __restrict__ w,
                                                          const float* __restrict__ b) {
    int ri = blockIdx.x;
    float* zr = z + (size_t)ri * E_;
    int t = threadIdx.x;
    float v[4]; float s = 0.f, s2 = 0.f;
#pragma unroll
    for (int i = 0; i < 4; i++) {
        int c = t + 256 * i;
        float u = zr[c];
        v[i] = u; s += u; s2 += u * u;
    }
    __shared__ float sh[2][8];
#pragma unroll
    for (int o = 16; o > 0; o >>= 1) {
        s  += __shfl_down_sync(0xFFFFFFFFu, s, o);
        s2 += __shfl_down_sync(0xFFFFFFFFu, s2, o);
    }
    int wid = t >> 5, lane = t & 31;
    if (lane == 0) { sh[0][wid] = s; sh[1][wid] = s2; }
    __syncthreads();
    if (t == 0) {
        float a = 0.f, c2 = 0.f;
#pragma unroll
        for (int i = 0; i < 8; i++) { a += sh[0][i]; c2 += sh[1][i]; }
        sh[0][0] = a; sh[1][0] = c2;
    }
    __syncthreads();
    float mean = sh[0][0] * (1.f / E_);
    float var  = sh[1][0] * (1.f / E_) - mean * mean;
    float rs   = rsqrtf(var + 1e-5f);
#pragma unroll
    for (int i = 0; i < 4; i++) {
        int c = t + 256 * i;
        zr[c] = (v[i] - mean) * rs * w[c] + b[c];
    }
}

// ---------------------------------------------------------------------------
// Launch
// ---------------------------------------------------------------------------
extern "C" void kernel_launch(void* const* d_in, const int* in_sizes, int n_in,
                              void* d_out, int out_size) {
    const float* x     = (const float*)d_in[0];
    const float* w_v   = (const float*)d_in[3];
    const float* w_o   = (const float*)d_in[4];
    const float* b_o   = (const float*)d_in[5];
    const float* ln1_w = (const float*)d_in[6];
    const float* ln1_b = (const float*)d_in[7];
    const float* ln2_w = (const float*)d_in[8];
    const float* ln2_b = (const float*)d_in[9];
    const float* w_ff1 = (const float*)d_in[10];
    const float* b_ff1 = (const float*)d_in[11];
    const float* w_ff2 = (const float*)d_in[12];
    const float* b_ff2 = (const float*)d_in[13];
    float* out = (float*)d_out;

    float *p_S, *p_AOproj, *p_h1;
    __nv_bfloat16 *p_h1h, *p_h1l, *p_th, *p_tl, *p_wt1h, *p_wt1l, *p_wt2h, *p_wt2l;
    cudaGetSymbolAddress((void**)&p_S, g_S);
    cudaGetSymbolAddress((void**)&p_AOproj, g_AOproj);
    cudaGetSymbolAddress((void**)&p_h1, g_h1);
    cudaGetSymbolAddress((void**)&p_h1h, g_h1h);
    cudaGetSymbolAddress((void**)&p_h1l, g_h1l);
    cudaGetSymbolAddress((void**)&p_th, g_th);
    cudaGetSymbolAddress((void**)&p_tl, g_tl);
    cudaGetSymbolAddress((void**)&p_wt1h, g_wt1h);
    cudaGetSymbolAddress((void**)&p_wt1l, g_wt1l);
    cudaGetSymbolAddress((void**)&p_wt2h, g_wt2h);
    cudaGetSymbolAddress((void**)&p_wt2l, g_wt2l);

    cudaFuncSetAttribute(hmma_gemm_kernel<1>, cudaFuncAttributeMaxDynamicSharedMemorySize, SMEM_BYTES);
    cudaFuncSetAttribute(hmma_gemm_kernel<2>, cudaFuncAttributeMaxDynamicSharedMemorySize, SMEM_BYTES);

    // 1) wv_red; 2) S = x @ wv_red
    reduce_wv_kernel<<<E_, DH>>>(w_v);
    gemm_S_kernel<<<ROWS / 4, dim3(64, 4)>>>(x);

    // 3) AOproj = S(1024x1024) @ w_o + b_o   (fp32, small)
    sgemm128_kernel<<<dim3(E_ / 128, (B_ * 256) / 128), 256>>>(
        B_ * 256, E_, E_, p_S, w_o, p_AOproj, b_o);

    // 4) h1 = LN1(AOproj[gather] + x), plus bf16 split
    add_ln1_kernel<<<ROWS, 256>>>(x, ln1_w, ln1_b);

    // 5) transpose+split weights: wt1[HID,E] from w_ff1[E,HID]; wt2[E,HID] from w_ff2[HID,E]
    transpose_split_kernel<<<dim3(HID_ / 32, E_ / 32), dim3(32, 8)>>>(w_ff1, E_, HID_, p_wt1h, p_wt1l);
    transpose_split_kernel<<<dim3(E_ / 32, HID_ / 32), dim3(32, 8)>>>(w_ff2, HID_, E_, p_wt2h, p_wt2l);

    // 6) t = relu(h1 @ w_ff1 + b_ff1) -> bf16 split   (HMMA)
    hmma_gemm_kernel<1><<<dim3(HID_ / 128, ROWS / 128), 256, SMEM_BYTES>>>(
        ROWS, HID_, E_, p_h1h, p_h1l, p_wt1h, p_wt1l, b_ff1, nullptr, nullptr, p_th, p_tl);

    // 7) out = t @ w_ff2 + b_ff2 + h1   (HMMA)
    hmma_gemm_kernel<2><<<dim3(E_ / 128, ROWS / 128), 256, SMEM_BYTES>>>(
        ROWS, E_, HID_, p_th, p_tl, p_wt2h, p_wt2l, b_ff2, p_h1, out, nullptr, nullptr);

    // 8) LN2 in-place
    ln2_inplace_kernel<<<ROWS, 256>>>(out, ln2_w, ln2_b);
}